// round 1
// baseline (speedup 1.0000x reference)
#include <cuda_runtime.h>
#include <cuda_bf16.h>
#include <math.h>

// SimDiff: right[f,i] = cos(x[f,i], x[f+interval, i+1])        (i < tpf-1)
//          down [f,i] = cos(x[f,i], x[f+interval, i+width])    (i < tpf-width)
// all other positions -1. Output: [right_full | down_full], each frames*tpf f32.
//
// One warp per token (f,i): anchor vector cached in registers (NPL float4 per
// lane), both neighbor vectors streamed against it. 5 warp-reductions
// (|a|^2, a.b1, |b1|^2, a.b2, |b2|^2), lane 0 writes both outputs.

#define EPSN 1e-8f

template <int NPL>  // float4 elements per lane; D = NPL * 128
__global__ void __launch_bounds__(256) simdiff_reg_kernel(
    const float* __restrict__ x,
    const int* __restrict__ p_frames,
    const int* __restrict__ p_height,
    const int* __restrict__ p_width,
    const int* __restrict__ p_interval,
    float* __restrict__ out,
    int total)  // frames * tpf
{
    const int gwarp = (blockIdx.x * blockDim.x + threadIdx.x) >> 5;
    const int lane  = threadIdx.x & 31;
    if (gwarp >= total) return;

    const int width    = *p_width;
    const int height   = *p_height;
    const int frames   = *p_frames;
    const int interval = *p_interval;
    const int tpf      = width * height;
    const int D        = NPL * 128;

    const int f = gwarp / tpf;
    const int i = gwarp - f * tpf;

    const bool vf = (f + interval) < frames;
    const bool vr = vf && (i < tpf - 1);
    const bool vd = vf && (i < tpf - width);

    float* __restrict__ outR = out;
    float* __restrict__ outD = out + total;

    if (!vr && !vd) {
        if (lane == 0) { outR[gwarp] = -1.0f; outD[gwarp] = -1.0f; }
        return;
    }

    // Anchor vector a = x[f, i], cached in registers.
    const float4* __restrict__ a4 =
        reinterpret_cast<const float4*>(x + (size_t)gwarp * D);
    float4 av[NPL];
    float na = 0.0f;
#pragma unroll
    for (int k = 0; k < NPL; k++) {
        float4 v = a4[lane + 32 * k];
        av[k] = v;
        na = fmaf(v.x, v.x, na); na = fmaf(v.y, v.y, na);
        na = fmaf(v.z, v.z, na); na = fmaf(v.w, v.w, na);
    }

    const size_t bframe = ((size_t)(f + interval) * tpf + i);

    float d1 = 0.0f, n1 = 0.0f;
    if (vr) {
        const float4* __restrict__ b4 =
            reinterpret_cast<const float4*>(x + (bframe + 1) * D);
#pragma unroll
        for (int k = 0; k < NPL; k++) {
            float4 b = b4[lane + 32 * k];
            float4 a = av[k];
            d1 = fmaf(a.x, b.x, d1); d1 = fmaf(a.y, b.y, d1);
            d1 = fmaf(a.z, b.z, d1); d1 = fmaf(a.w, b.w, d1);
            n1 = fmaf(b.x, b.x, n1); n1 = fmaf(b.y, b.y, n1);
            n1 = fmaf(b.z, b.z, n1); n1 = fmaf(b.w, b.w, n1);
        }
    }

    float d2 = 0.0f, n2 = 0.0f;
    if (vd) {
        const float4* __restrict__ b4 =
            reinterpret_cast<const float4*>(x + (bframe + width) * D);
#pragma unroll
        for (int k = 0; k < NPL; k++) {
            float4 b = b4[lane + 32 * k];
            float4 a = av[k];
            d2 = fmaf(a.x, b.x, d2); d2 = fmaf(a.y, b.y, d2);
            d2 = fmaf(a.z, b.z, d2); d2 = fmaf(a.w, b.w, d2);
            n2 = fmaf(b.x, b.x, n2); n2 = fmaf(b.y, b.y, n2);
            n2 = fmaf(b.z, b.z, n2); n2 = fmaf(b.w, b.w, n2);
        }
    }

    // Warp butterfly reduce 5 accumulators.
#pragma unroll
    for (int off = 16; off > 0; off >>= 1) {
        na += __shfl_xor_sync(0xFFFFFFFFu, na, off);
        d1 += __shfl_xor_sync(0xFFFFFFFFu, d1, off);
        n1 += __shfl_xor_sync(0xFFFFFFFFu, n1, off);
        d2 += __shfl_xor_sync(0xFFFFFFFFu, d2, off);
        n2 += __shfl_xor_sync(0xFFFFFFFFu, n2, off);
    }

    if (lane == 0) {
        const float nA = fmaxf(sqrtf(na), EPSN);
        outR[gwarp] = vr ? d1 / (nA * fmaxf(sqrtf(n1), EPSN)) : -1.0f;
        outD[gwarp] = vd ? d2 / (nA * fmaxf(sqrtf(n2), EPSN)) : -1.0f;
    }
}

// Generic fallback for D not a multiple of 128 (scalar loads, a streamed twice).
__global__ void __launch_bounds__(256) simdiff_generic_kernel(
    const float* __restrict__ x,
    const int* __restrict__ p_frames,
    const int* __restrict__ p_height,
    const int* __restrict__ p_width,
    const int* __restrict__ p_interval,
    float* __restrict__ out,
    int total, int D)
{
    const int gwarp = (blockIdx.x * blockDim.x + threadIdx.x) >> 5;
    const int lane  = threadIdx.x & 31;
    if (gwarp >= total) return;

    const int width    = *p_width;
    const int height   = *p_height;
    const int frames   = *p_frames;
    const int interval = *p_interval;
    const int tpf      = width * height;

    const int f = gwarp / tpf;
    const int i = gwarp - f * tpf;

    const bool vf = (f + interval) < frames;
    const bool vr = vf && (i < tpf - 1);
    const bool vd = vf && (i < tpf - width);

    float* __restrict__ outR = out;
    float* __restrict__ outD = out + total;

    if (!vr && !vd) {
        if (lane == 0) { outR[gwarp] = -1.0f; outD[gwarp] = -1.0f; }
        return;
    }

    const float* a = x + (size_t)gwarp * D;
    const size_t bframe = ((size_t)(f + interval) * tpf + i);

    float na = 0.0f, d1 = 0.0f, n1 = 0.0f, d2 = 0.0f, n2 = 0.0f;
    for (int k = lane; k < D; k += 32) {
        float av = a[k];
        na = fmaf(av, av, na);
        if (vr) {
            float b = x[(bframe + 1) * D + k];
            d1 = fmaf(av, b, d1); n1 = fmaf(b, b, n1);
        }
        if (vd) {
            float b = x[(bframe + width) * D + k];
            d2 = fmaf(av, b, d2); n2 = fmaf(b, b, n2);
        }
    }

#pragma unroll
    for (int off = 16; off > 0; off >>= 1) {
        na += __shfl_xor_sync(0xFFFFFFFFu, na, off);
        d1 += __shfl_xor_sync(0xFFFFFFFFu, d1, off);
        n1 += __shfl_xor_sync(0xFFFFFFFFu, n1, off);
        d2 += __shfl_xor_sync(0xFFFFFFFFu, d2, off);
        n2 += __shfl_xor_sync(0xFFFFFFFFu, n2, off);
    }

    if (lane == 0) {
        const float nA = fmaxf(sqrtf(na), EPSN);
        outR[gwarp] = vr ? d1 / (nA * fmaxf(sqrtf(n1), EPSN)) : -1.0f;
        outD[gwarp] = vd ? d2 / (nA * fmaxf(sqrtf(n2), EPSN)) : -1.0f;
    }
}

extern "C" void kernel_launch(void* const* d_in, const int* in_sizes, int n_in,
                              void* d_out, int out_size) {
    const float* x        = (const float*)d_in[0];
    const int* p_frames   = (const int*)d_in[1];
    const int* p_height   = (const int*)d_in[2];
    const int* p_width    = (const int*)d_in[3];
    const int* p_interval = (const int*)d_in[4];
    float* out = (float*)d_out;

    const int total = out_size / 2;            // frames * tpf
    const int D     = in_sizes[0] / total;     // hidden dim

    const int threads = 256;                   // 8 warps/block
    const int blocks  = (total + 7) / 8;

    if (D == 1152) {
        simdiff_reg_kernel<9><<<blocks, threads>>>(
            x, p_frames, p_height, p_width, p_interval, out, total);
    } else if (D == 1024) {
        simdiff_reg_kernel<8><<<blocks, threads>>>(
            x, p_frames, p_height, p_width, p_interval, out, total);
    } else if (D == 1280) {
        simdiff_reg_kernel<10><<<blocks, threads>>>(
            x, p_frames, p_height, p_width, p_interval, out, total);
    } else {
        simdiff_generic_kernel<<<blocks, threads>>>(
            x, p_frames, p_height, p_width, p_interval, out, total, D);
    }
}

// round 2
// speedup vs baseline: 1.3745x; 1.3745x over previous
#include <cuda_runtime.h>
#include <cuda_bf16.h>
#include <math.h>

// SimDiff: right[f,i] = cos(x[f,i], x[f+interval, i+1])        (i < tpf-1)
//          down [f,i] = cos(x[f,i], x[f+interval, i+width])    (i < tpf-width)
// all other positions -1. Output: [right_full | down_full], each frames*tpf f32.
//
// One warp per token. Streaming version: all three vectors (anchor, right-
// neighbor, down-neighbor) are streamed with double-buffered float4 loads.
// Low register count (~40) -> 6 blocks/SM -> high occupancy to hide DRAM
// latency. Invalid neighbors are clamped to a safe in-bounds address and the
// output fixed up with -1 (edge warps do throwaway math; keeps the hot loop
// predicate-free).

#define EPSN 1e-8f

template <int NPL>  // float4 elements per lane; D = NPL * 128
__global__ void __launch_bounds__(256, 6) simdiff_stream_kernel(
    const float* __restrict__ x,
    const int* __restrict__ p_frames,
    const int* __restrict__ p_height,
    const int* __restrict__ p_width,
    const int* __restrict__ p_interval,
    float* __restrict__ out,
    int total)  // frames * tpf
{
    const int gwarp = (blockIdx.x * blockDim.x + threadIdx.x) >> 5;
    const int lane  = threadIdx.x & 31;
    if (gwarp >= total) return;

    const int width    = *p_width;
    const int height   = *p_height;
    const int frames   = *p_frames;
    const int interval = *p_interval;
    const int tpf      = width * height;
    const int D        = NPL * 128;

    const int f = gwarp / tpf;
    const int i = gwarp - f * tpf;

    float* __restrict__ outR = out;
    float* __restrict__ outD = out + total;

    const bool vf = (f + interval) < frames;
    if (!vf) {
        if (lane == 0) { outR[gwarp] = -1.0f; outD[gwarp] = -1.0f; }
        return;
    }
    const bool vr = (i < tpf - 1);
    const bool vd = (i < tpf - width);

    const size_t bframe = (size_t)(f + interval) * tpf + i;
    // Clamp invalid neighbors to a safe in-bounds vector (bframe itself);
    // results for those are discarded below.
    const size_t i1 = vr ? (bframe + 1)     : bframe;
    const size_t i2 = vd ? (bframe + width) : bframe;

    const float4* __restrict__ a4 =
        reinterpret_cast<const float4*>(x + (size_t)gwarp * D) + lane;
    const float4* __restrict__ b4 =
        reinterpret_cast<const float4*>(x + i1 * D) + lane;
    const float4* __restrict__ c4 =
        reinterpret_cast<const float4*>(x + i2 * D) + lane;

    float na = 0.0f, d1 = 0.0f, n1 = 0.0f, d2 = 0.0f, n2 = 0.0f;

    // Software double buffering: loads for iteration k+1 issued before the
    // FMAs of iteration k, so 3 loads are always in flight per warp.
    float4 a = a4[0];
    float4 b = b4[0];
    float4 c = c4[0];
#pragma unroll
    for (int k = 0; k < NPL; k++) {
        float4 ac = a, bc = b, cc = c;
        if (k + 1 < NPL) {
            a = a4[32 * (k + 1)];
            b = b4[32 * (k + 1)];
            c = c4[32 * (k + 1)];
        }
        na = fmaf(ac.x, ac.x, na); na = fmaf(ac.y, ac.y, na);
        na = fmaf(ac.z, ac.z, na); na = fmaf(ac.w, ac.w, na);
        d1 = fmaf(ac.x, bc.x, d1); d1 = fmaf(ac.y, bc.y, d1);
        d1 = fmaf(ac.z, bc.z, d1); d1 = fmaf(ac.w, bc.w, d1);
        n1 = fmaf(bc.x, bc.x, n1); n1 = fmaf(bc.y, bc.y, n1);
        n1 = fmaf(bc.z, bc.z, n1); n1 = fmaf(bc.w, bc.w, n1);
        d2 = fmaf(ac.x, cc.x, d2); d2 = fmaf(ac.y, cc.y, d2);
        d2 = fmaf(ac.z, cc.z, d2); d2 = fmaf(ac.w, cc.w, d2);
        n2 = fmaf(cc.x, cc.x, n2); n2 = fmaf(cc.y, cc.y, n2);
        n2 = fmaf(cc.z, cc.z, n2); n2 = fmaf(cc.w, cc.w, n2);
    }

    // Warp butterfly reduce 5 accumulators.
#pragma unroll
    for (int off = 16; off > 0; off >>= 1) {
        na += __shfl_xor_sync(0xFFFFFFFFu, na, off);
        d1 += __shfl_xor_sync(0xFFFFFFFFu, d1, off);
        n1 += __shfl_xor_sync(0xFFFFFFFFu, n1, off);
        d2 += __shfl_xor_sync(0xFFFFFFFFu, d2, off);
        n2 += __shfl_xor_sync(0xFFFFFFFFu, n2, off);
    }

    if (lane == 0) {
        const float nA = fmaxf(sqrtf(na), EPSN);
        outR[gwarp] = vr ? d1 / (nA * fmaxf(sqrtf(n1), EPSN)) : -1.0f;
        outD[gwarp] = vd ? d2 / (nA * fmaxf(sqrtf(n2), EPSN)) : -1.0f;
    }
}

// Generic fallback for arbitrary D (scalar loads).
__global__ void __launch_bounds__(256) simdiff_generic_kernel(
    const float* __restrict__ x,
    const int* __restrict__ p_frames,
    const int* __restrict__ p_height,
    const int* __restrict__ p_width,
    const int* __restrict__ p_interval,
    float* __restrict__ out,
    int total, int D)
{
    const int gwarp = (blockIdx.x * blockDim.x + threadIdx.x) >> 5;
    const int lane  = threadIdx.x & 31;
    if (gwarp >= total) return;

    const int width    = *p_width;
    const int height   = *p_height;
    const int frames   = *p_frames;
    const int interval = *p_interval;
    const int tpf      = width * height;

    const int f = gwarp / tpf;
    const int i = gwarp - f * tpf;

    float* __restrict__ outR = out;
    float* __restrict__ outD = out + total;

    const bool vf = (f + interval) < frames;
    if (!vf) {
        if (lane == 0) { outR[gwarp] = -1.0f; outD[gwarp] = -1.0f; }
        return;
    }
    const bool vr = (i < tpf - 1);
    const bool vd = (i < tpf - width);

    const size_t bframe = (size_t)(f + interval) * tpf + i;
    const size_t i1 = vr ? (bframe + 1)     : bframe;
    const size_t i2 = vd ? (bframe + width) : bframe;

    const float* a = x + (size_t)gwarp * D;
    const float* b = x + i1 * D;
    const float* c = x + i2 * D;

    float na = 0.0f, d1 = 0.0f, n1 = 0.0f, d2 = 0.0f, n2 = 0.0f;
    for (int k = lane; k < D; k += 32) {
        float av = a[k], bv = b[k], cv = c[k];
        na = fmaf(av, av, na);
        d1 = fmaf(av, bv, d1); n1 = fmaf(bv, bv, n1);
        d2 = fmaf(av, cv, d2); n2 = fmaf(cv, cv, n2);
    }

#pragma unroll
    for (int off = 16; off > 0; off >>= 1) {
        na += __shfl_xor_sync(0xFFFFFFFFu, na, off);
        d1 += __shfl_xor_sync(0xFFFFFFFFu, d1, off);
        n1 += __shfl_xor_sync(0xFFFFFFFFu, n1, off);
        d2 += __shfl_xor_sync(0xFFFFFFFFu, d2, off);
        n2 += __shfl_xor_sync(0xFFFFFFFFu, n2, off);
    }

    if (lane == 0) {
        const float nA = fmaxf(sqrtf(na), EPSN);
        outR[gwarp] = vr ? d1 / (nA * fmaxf(sqrtf(n1), EPSN)) : -1.0f;
        outD[gwarp] = vd ? d2 / (nA * fmaxf(sqrtf(n2), EPSN)) : -1.0f;
    }
}

extern "C" void kernel_launch(void* const* d_in, const int* in_sizes, int n_in,
                              void* d_out, int out_size) {
    const float* x        = (const float*)d_in[0];
    const int* p_frames   = (const int*)d_in[1];
    const int* p_height   = (const int*)d_in[2];
    const int* p_width    = (const int*)d_in[3];
    const int* p_interval = (const int*)d_in[4];
    float* out = (float*)d_out;

    const int total = out_size / 2;            // frames * tpf
    const int D     = in_sizes[0] / total;     // hidden dim

    const int threads = 256;                   // 8 warps/block
    const int blocks  = (total + 7) / 8;

    if (D == 1152) {
        simdiff_stream_kernel<9><<<blocks, threads>>>(
            x, p_frames, p_height, p_width, p_interval, out, total);
    } else if (D == 1024) {
        simdiff_stream_kernel<8><<<blocks, threads>>>(
            x, p_frames, p_height, p_width, p_interval, out, total);
    } else if (D == 1280) {
        simdiff_stream_kernel<10><<<blocks, threads>>>(
            x, p_frames, p_height, p_width, p_interval, out, total);
    } else {
        simdiff_generic_kernel<<<blocks, threads>>>(
            x, p_frames, p_height, p_width, p_interval, out, total, D);
    }
}